// round 12
// baseline (speedup 1.0000x reference)
#include <cuda_runtime.h>
#include <cuda_fp16.h>
#include <cstdint>

#define NN 50000
#define EE 800000
#define SCAN_BLK ((NN + 1023) / 1024)   // 49

// ---------------- device scratch (no allocations allowed) ----------------
__device__ __align__(16) int    g_outdeg[NN];
__device__ __align__(16) int    g_indeg[NN];
__device__ __align__(16) int    g_cursor[NN];
__device__ __align__(16) int    g_rowptr[NN + 1];
__device__ __align__(16) int    g_esrc[EE];
__device__ __align__(16) int    g_bsum[SCAN_BLK];
__device__ __align__(16) float  g_norm_src[NN];
__device__ __align__(16) float  g_norm_dst[NN];
__device__ __align__(16) __half g_x16[(size_t)NN * 64];
__device__ __align__(16) __half g_agg1[(size_t)NN * 64];
__device__ __align__(16) __half g_h1[(size_t)NN * 128];
__device__ __align__(16) __half g_h2[(size_t)NN * 64];

__device__ __forceinline__ uint32_t f2tf32(float v) {
    uint32_t u;
    asm("cvt.rna.tf32.f32 %0, %1;" : "=r"(u) : "f"(v));
    return u;
}

#define MMA_TF32(c0, c1, c2, c3, a0, a1, a2, a3, b0, b1) \
    asm volatile("mma.sync.aligned.m16n8k8.row.col.f32.tf32.tf32.f32 " \
        "{%0,%1,%2,%3}, {%4,%5,%6,%7}, {%8,%9}, {%0,%1,%2,%3};" \
        : "+f"(c0), "+f"(c1), "+f"(c2), "+f"(c3) \
        : "r"(a0), "r"(a1), "r"(a2), "r"(a3), "r"(b0), "r"(b1))

__device__ __forceinline__ void h8_to_f8(uint4 raw, float* f) {
    float2 p;
    p = __half22float2(*reinterpret_cast<__half2*>(&raw.x)); f[0] = p.x; f[1] = p.y;
    p = __half22float2(*reinterpret_cast<__half2*>(&raw.y)); f[2] = p.x; f[3] = p.y;
    p = __half22float2(*reinterpret_cast<__half2*>(&raw.z)); f[4] = p.x; f[5] = p.y;
    p = __half22float2(*reinterpret_cast<__half2*>(&raw.w)); f[6] = p.x; f[7] = p.y;
}

// ---------------- preprocessing ----------------
__global__ void k_convzero(const float* __restrict__ x) {
    int i = blockIdx.x * blockDim.x + threadIdx.x;   // [0, NN*8)
    if (i < NN * 8) {
        const float4* xp = reinterpret_cast<const float4*>(x) + (size_t)i * 2;
        float4 a = xp[0], b = xp[1];
        uint4 o;
        *reinterpret_cast<__half2*>(&o.x) = __floats2half2_rn(a.x, a.y);
        *reinterpret_cast<__half2*>(&o.y) = __floats2half2_rn(a.z, a.w);
        *reinterpret_cast<__half2*>(&o.z) = __floats2half2_rn(b.x, b.y);
        *reinterpret_cast<__half2*>(&o.w) = __floats2half2_rn(b.z, b.w);
        reinterpret_cast<uint4*>(g_x16)[i] = o;
    }
    if (i < NN) { g_outdeg[i] = 0; g_indeg[i] = 0; }
}

// scalar 1-edge-per-thread (R9-proven: atomic throughput wants many warps)
__global__ void k_degree(const int* __restrict__ src, const int* __restrict__ dst) {
    int e = blockIdx.x * blockDim.x + threadIdx.x;
    if (e < EE) {
        atomicAdd(&g_outdeg[src[e]], 1);
        atomicAdd(&g_indeg[dst[e]], 1);
    }
}

// per-block inclusive scan of indeg; norms fused
__global__ void k_scan_blk() {
    __shared__ int sh[1024];
    int t = threadIdx.x;
    int i = blockIdx.x * 1024 + t;
    int deg = (i < NN) ? g_indeg[i] : 0;
    if (i < NN) {
        g_norm_dst[i] = rsqrtf((float)max(deg, 1));
        g_norm_src[i] = rsqrtf((float)max(g_outdeg[i], 1));
    }
    sh[t] = deg;
    __syncthreads();
    #pragma unroll
    for (int off = 1; off < 1024; off <<= 1) {
        int x = (t >= off) ? sh[t - off] : 0;
        __syncthreads();
        sh[t] += x;
        __syncthreads();
    }
    if (i < NN) g_rowptr[i + 1] = sh[t];
    if (t == 1023) g_bsum[blockIdx.x] = sh[1023];
}

__global__ void k_scan_add() {
    __shared__ int off;
    int t = threadIdx.x;
    int i = blockIdx.x * 1024 + t;
    if (t < 32) {
        int s = 0;
        for (int b = t; b < blockIdx.x; b += 32) s += g_bsum[b];
        #pragma unroll
        for (int o = 16; o > 0; o >>= 1) s += __shfl_down_sync(0xFFFFFFFFu, s, o);
        if (t == 0) off = s;
    }
    __syncthreads();
    if (i < NN) {
        int v = g_rowptr[i + 1] + off;
        g_rowptr[i + 1] = v;
        if (i + 1 < NN) g_cursor[i + 1] = v;
        if (i == 0) { g_rowptr[0] = 0; g_cursor[0] = 0; }
    }
}

// scalar 1-edge-per-thread (R9-proven)
__global__ void k_scatter(const int* __restrict__ src, const int* __restrict__ dst) {
    int e = blockIdx.x * blockDim.x + threadIdx.x;
    if (e < EE) {
        int pos = atomicAdd(&g_cursor[dst[e]], 1);
        g_esrc[pos] = src[e];
    }
}

// ---------------- aggregation: one warp per node, 4 edge slots x 8 lanes x 16B ----------------
// Single change vs R9: unroll 2 -> 4 (16 feature loads in flight/warp, no extra regs/shuffles)
template <bool LAYER1>
__global__ void __launch_bounds__(256) k_agg(const float* __restrict__ bias,
                                             float* __restrict__ out_arg) {
    const uint4* __restrict__ feat = LAYER1
        ? reinterpret_cast<const uint4*>(g_x16)
        : reinterpret_cast<const uint4*>(g_h2);
    int n = blockIdx.x * 8 + (threadIdx.x >> 5);   // grid*8 == NN
    int lane = threadIdx.x & 31;
    int slot = lane >> 3;        // 4 slots
    int fl   = lane & 7;         // 8 lanes/slot, 8 halves each

    int s = g_rowptr[n], e = g_rowptr[n + 1];
    float acc[8] = {0.f, 0.f, 0.f, 0.f, 0.f, 0.f, 0.f, 0.f};
    #pragma unroll 4
    for (int j = s + slot; j < e; j += 4) {
        int u = g_esrc[j];
        uint4 raw = feat[(size_t)u * 8 + fl];
        float f[8];
        h8_to_f8(raw, f);
        if (LAYER1) {
            float sc = g_norm_src[u];
            #pragma unroll
            for (int k = 0; k < 8; k++) acc[k] = fmaf(f[k], sc, acc[k]);
        } else {
            #pragma unroll
            for (int k = 0; k < 8; k++) acc[k] += f[k];
        }
    }
    #pragma unroll
    for (int o = 16; o >= 8; o >>= 1)
        #pragma unroll
        for (int k = 0; k < 8; k++)
            acc[k] += __shfl_down_sync(0xFFFFFFFFu, acc[k], o);

    if (slot == 0) {
        if (LAYER1) {
            uint4 o;
            *reinterpret_cast<__half2*>(&o.x) = __floats2half2_rn(acc[0], acc[1]);
            *reinterpret_cast<__half2*>(&o.y) = __floats2half2_rn(acc[2], acc[3]);
            *reinterpret_cast<__half2*>(&o.z) = __floats2half2_rn(acc[4], acc[5]);
            *reinterpret_cast<__half2*>(&o.w) = __floats2half2_rn(acc[6], acc[7]);
            reinterpret_cast<uint4*>(g_agg1)[(size_t)n * 8 + fl] = o;
        } else {
            float nd = g_norm_dst[n];
            float4 b0 = reinterpret_cast<const float4*>(bias)[fl * 2];
            float4 b1 = reinterpret_cast<const float4*>(bias)[fl * 2 + 1];
            float* op = out_arg + (size_t)n * 64 + fl * 8;
            *reinterpret_cast<float4*>(op) = make_float4(
                fmaf(acc[0], nd, b0.x), fmaf(acc[1], nd, b0.y),
                fmaf(acc[2], nd, b0.z), fmaf(acc[3], nd, b0.w));
            *reinterpret_cast<float4*>(op + 4) = make_float4(
                fmaf(acc[4], nd, b1.x), fmaf(acc[5], nd, b1.y),
                fmaf(acc[6], nd, b1.z), fmaf(acc[7], nd, b1.w));
        }
    }
}

// ---------------- GEMM 1 (tf32 mma.sync): h1 = relu((agg1 @ W1)*nd + b1) ----------------
#define G1_AS_STRIDE 76
#define G1_WS_STRIDE 132
#define G1_WS_OFF  (128 * G1_AS_STRIDE)
#define G1_B1_OFF  (G1_WS_OFF + 64 * G1_WS_STRIDE)
#define G1_SMEM    ((G1_B1_OFF + 128) * 4)

__global__ void __launch_bounds__(256) k_gemm1_mma(const float* __restrict__ W1,
                                                   const float* __restrict__ b1) {
    extern __shared__ float sm[];
    float* As  = sm;
    float* Ws  = sm + G1_WS_OFF;
    float* sb1 = sm + G1_B1_OFF;

    int tid = threadIdx.x;
    int row0 = blockIdx.x * 128;

    #pragma unroll
    for (int it = 0; it < 4; it++) {
        int idx = tid + it * 256;
        int r = idx >> 3, c8 = idx & 7;
        int row = row0 + r;
        float f[8] = {0.f, 0.f, 0.f, 0.f, 0.f, 0.f, 0.f, 0.f};
        if (row < NN) {
            uint4 raw = reinterpret_cast<const uint4*>(g_agg1)[(size_t)row * 8 + c8];
            h8_to_f8(raw, f);
        }
        float* p = &As[r * G1_AS_STRIDE + c8 * 8];
        #pragma unroll
        for (int k = 0; k < 8; k++) p[k] = __uint_as_float(f2tf32(f[k]));
    }
    #pragma unroll
    for (int it = 0; it < 8; it++) {
        int idx4 = tid + it * 256;
        int k = idx4 >> 5, c4 = idx4 & 31;
        float4 v = *reinterpret_cast<const float4*>(&W1[(size_t)k * 128 + c4 * 4]);
        float* p = &Ws[k * G1_WS_STRIDE + c4 * 4];
        p[0] = __uint_as_float(f2tf32(v.x)); p[1] = __uint_as_float(f2tf32(v.y));
        p[2] = __uint_as_float(f2tf32(v.z)); p[3] = __uint_as_float(f2tf32(v.w));
    }
    if (tid < 128) sb1[tid] = b1[tid];
    __syncthreads();

    int w = tid >> 5, lane = tid & 31;
    int wr = w >> 1, wc = w & 1;
    int g = lane >> 2, t4 = lane & 3;

    float c[2][8][4];
    #pragma unroll
    for (int i = 0; i < 2; i++)
        #pragma unroll
        for (int j = 0; j < 8; j++)
            #pragma unroll
            for (int q = 0; q < 4; q++) c[i][j][q] = 0.f;

    const uint32_t* Au = reinterpret_cast<const uint32_t*>(As);
    const uint32_t* Wu = reinterpret_cast<const uint32_t*>(Ws);

    #pragma unroll
    for (int ks = 0; ks < 8; ks++) {
        int kb = ks * 8;
        uint32_t a[2][4];
        #pragma unroll
        for (int rf = 0; rf < 2; rf++) {
            int R = wr * 32 + rf * 16;
            a[rf][0] = Au[(R + g) * G1_AS_STRIDE + kb + t4];
            a[rf][1] = Au[(R + 8 + g) * G1_AS_STRIDE + kb + t4];
            a[rf][2] = Au[(R + g) * G1_AS_STRIDE + kb + 4 + t4];
            a[rf][3] = Au[(R + 8 + g) * G1_AS_STRIDE + kb + 4 + t4];
        }
        #pragma unroll
        for (int cf = 0; cf < 8; cf++) {
            int C = wc * 64 + cf * 8 + g;
            uint32_t b0 = Wu[(kb + t4) * G1_WS_STRIDE + C];
            uint32_t b1r = Wu[(kb + 4 + t4) * G1_WS_STRIDE + C];
            #pragma unroll
            for (int rf = 0; rf < 2; rf++)
                MMA_TF32(c[rf][cf][0], c[rf][cf][1], c[rf][cf][2], c[rf][cf][3],
                         a[rf][0], a[rf][1], a[rf][2], a[rf][3], b0, b1r);
        }
    }

    #pragma unroll
    for (int rf = 0; rf < 2; rf++) {
        int r1 = row0 + wr * 32 + rf * 16 + g;
        int r2 = r1 + 8;
        float nd1 = (r1 < NN) ? g_norm_dst[r1] : 0.f;
        float nd2 = (r2 < NN) ? g_norm_dst[r2] : 0.f;
        #pragma unroll
        for (int cf = 0; cf < 8; cf++) {
            int col = wc * 64 + cf * 8 + 2 * t4;
            float bx = sb1[col], by = sb1[col + 1];
            if (r1 < NN)
                *reinterpret_cast<__half2*>(&g_h1[(size_t)r1 * 128 + col]) =
                    __floats2half2_rn(fmaxf(fmaf(c[rf][cf][0], nd1, bx), 0.f),
                                      fmaxf(fmaf(c[rf][cf][1], nd1, by), 0.f));
            if (r2 < NN)
                *reinterpret_cast<__half2*>(&g_h1[(size_t)r2 * 128 + col]) =
                    __floats2half2_rn(fmaxf(fmaf(c[rf][cf][2], nd2, bx), 0.f),
                                      fmaxf(fmaf(c[rf][cf][3], nd2, by), 0.f));
        }
    }
}

// ---------------- GEMM 2 (tf32 mma.sync): h2 = (h1 * norm_src) @ W2 ----------------
#define G2_AS_STRIDE 132
#define G2_WS_STRIDE 68
#define G2_WS_OFF  (128 * G2_AS_STRIDE)
#define G2_NS_OFF  (G2_WS_OFF + 128 * G2_WS_STRIDE)
#define G2_SMEM    ((G2_NS_OFF + 128) * 4)

__global__ void __launch_bounds__(256) k_gemm2_mma(const float* __restrict__ W2) {
    extern __shared__ float sm[];
    float* As  = sm;
    float* Ws  = sm + G2_WS_OFF;
    float* sns = sm + G2_NS_OFF;

    int tid = threadIdx.x;
    int row0 = blockIdx.x * 128;

    if (tid < 128) {
        int row = row0 + tid;
        sns[tid] = (row < NN) ? g_norm_src[row] : 0.f;
    }
    __syncthreads();

    #pragma unroll
    for (int it = 0; it < 8; it++) {
        int idx = tid + it * 256;
        int r = idx >> 4, c8 = idx & 15;
        int row = row0 + r;
        float f[8] = {0.f, 0.f, 0.f, 0.f, 0.f, 0.f, 0.f, 0.f};
        if (row < NN) {
            uint4 raw = reinterpret_cast<const uint4*>(g_h1)[(size_t)row * 16 + c8];
            h8_to_f8(raw, f);
        }
        float s = sns[r];
        float* p = &As[r * G2_AS_STRIDE + c8 * 8];
        #pragma unroll
        for (int k = 0; k < 8; k++) p[k] = __uint_as_float(f2tf32(f[k] * s));
    }
    #pragma unroll
    for (int it = 0; it < 8; it++) {
        int idx4 = tid + it * 256;
        int k = idx4 >> 4, c4 = idx4 & 15;
        float4 v = *reinterpret_cast<const float4*>(&W2[(size_t)k * 64 + c4 * 4]);
        float* p = &Ws[k * G2_WS_STRIDE + c4 * 4];
        p[0] = __uint_as_float(f2tf32(v.x)); p[1] = __uint_as_float(f2tf32(v.y));
        p[2] = __uint_as_float(f2tf32(v.z)); p[3] = __uint_as_float(f2tf32(v.w));
    }
    __syncthreads();

    int w = tid >> 5, lane = tid & 31;
    int wr = w >> 1, wc = w & 1;
    int g = lane >> 2, t4 = lane & 3;

    float c[2][4][4];
    #pragma unroll
    for (int i = 0; i < 2; i++)
        #pragma unroll
        for (int j = 0; j < 4; j++)
            #pragma unroll
            for (int q = 0; q < 4; q++) c[i][j][q] = 0.f;

    const uint32_t* Au = reinterpret_cast<const uint32_t*>(As);
    const uint32_t* Wu = reinterpret_cast<const uint32_t*>(Ws);

    #pragma unroll
    for (int ks = 0; ks < 16; ks++) {
        int kb = ks * 8;
        uint32_t a[2][4];
        #pragma unroll
        for (int rf = 0; rf < 2; rf++) {
            int R = wr * 32 + rf * 16;
            a[rf][0] = Au[(R + g) * G2_AS_STRIDE + kb + t4];
            a[rf][1] = Au[(R + 8 + g) * G2_AS_STRIDE + kb + t4];
            a[rf][2] = Au[(R + g) * G2_AS_STRIDE + kb + 4 + t4];
            a[rf][3] = Au[(R + 8 + g) * G2_AS_STRIDE + kb + 4 + t4];
        }
        #pragma unroll
        for (int cf = 0; cf < 4; cf++) {
            int C = wc * 32 + cf * 8 + g;
            uint32_t b0 = Wu[(kb + t4) * G2_WS_STRIDE + C];
            uint32_t b1r = Wu[(kb + 4 + t4) * G2_WS_STRIDE + C];
            #pragma unroll
            for (int rf = 0; rf < 2; rf++)
                MMA_TF32(c[rf][cf][0], c[rf][cf][1], c[rf][cf][2], c[rf][cf][3],
                         a[rf][0], a[rf][1], a[rf][2], a[rf][3], b0, b1r);
        }
    }

    #pragma unroll
    for (int rf = 0; rf < 2; rf++) {
        int r1 = row0 + wr * 32 + rf * 16 + g;
        int r2 = r1 + 8;
        #pragma unroll
        for (int cf = 0; cf < 4; cf++) {
            int col = wc * 32 + cf * 8 + 2 * t4;
            if (r1 < NN)
                *reinterpret_cast<__half2*>(&g_h2[(size_t)r1 * 64 + col]) =
                    __floats2half2_rn(c[rf][cf][0], c[rf][cf][1]);
            if (r2 < NN)
                *reinterpret_cast<__half2*>(&g_h2[(size_t)r2 * 64 + col]) =
                    __floats2half2_rn(c[rf][cf][2], c[rf][cf][3]);
        }
    }
}

// ---------------- launch ----------------
extern "C" void kernel_launch(void* const* d_in, const int* in_sizes, int n_in,
                              void* d_out, int out_size) {
    const float* x   = (const float*)d_in[0];
    const float* W1  = (const float*)d_in[1];
    const float* b1  = (const float*)d_in[2];
    const float* W2  = (const float*)d_in[3];
    const float* b2  = (const float*)d_in[4];
    const int*   src = (const int*)d_in[5];
    const int*   dst = (const int*)d_in[6];
    float* out = (float*)d_out;

    cudaFuncSetAttribute(k_gemm1_mma, cudaFuncAttributeMaxDynamicSharedMemorySize, G1_SMEM);
    cudaFuncSetAttribute(k_gemm2_mma, cudaFuncAttributeMaxDynamicSharedMemorySize, G2_SMEM);

    k_convzero<<<(NN * 8 + 255) / 256, 256>>>(x);
    k_degree<<<(EE + 255) / 256, 256>>>(src, dst);
    k_scan_blk<<<SCAN_BLK, 1024>>>();
    k_scan_add<<<SCAN_BLK, 1024>>>();
    k_scatter<<<(EE + 255) / 256, 256>>>(src, dst);

    int ntiles = (NN + 127) / 128;   // 391
    k_agg<true><<<NN / 8, 256>>>(nullptr, nullptr);
    k_gemm1_mma<<<ntiles, 256, G1_SMEM>>>(W1, b1);
    k_gemm2_mma<<<ntiles, 256, G2_SMEM>>>(W2);
    k_agg<false><<<NN / 8, 256>>>(b2, out);
}

// round 13
// speedup vs baseline: 1.1189x; 1.1189x over previous
#include <cuda_runtime.h>
#include <cuda_fp16.h>
#include <cstdint>

#define NN 50000
#define EE 800000
#define SCAN_BLK ((NN + 1023) / 1024)   // 49

// ---------------- device scratch (no allocations allowed) ----------------
__device__ __align__(16) int    g_outdeg[NN];
__device__ __align__(16) int    g_indeg[NN];
__device__ __align__(16) int    g_cursor[NN];
__device__ __align__(16) int    g_rowptr[NN + 1];
__device__ __align__(16) int    g_esrc[EE];
__device__ __align__(16) int    g_bsum[SCAN_BLK];
__device__ __align__(16) float  g_norm_src[NN];
__device__ __align__(16) float  g_norm_dst[NN];
__device__ __align__(16) __half g_x16[(size_t)NN * 64];
__device__ __align__(16) __half g_agg1[(size_t)NN * 64];
__device__ __align__(16) __half g_h2[(size_t)NN * 64];

__device__ __forceinline__ uint32_t f2tf32(float v) {
    uint32_t u;
    asm("cvt.rna.tf32.f32 %0, %1;" : "=r"(u) : "f"(v));
    return u;
}

#define MMA_TF32(c0, c1, c2, c3, a0, a1, a2, a3, b0, b1) \
    asm volatile("mma.sync.aligned.m16n8k8.row.col.f32.tf32.tf32.f32 " \
        "{%0,%1,%2,%3}, {%4,%5,%6,%7}, {%8,%9}, {%0,%1,%2,%3};" \
        : "+f"(c0), "+f"(c1), "+f"(c2), "+f"(c3) \
        : "r"(a0), "r"(a1), "r"(a2), "r"(a3), "r"(b0), "r"(b1))

__device__ __forceinline__ void h8_to_f8(uint4 raw, float* f) {
    float2 p;
    p = __half22float2(*reinterpret_cast<__half2*>(&raw.x)); f[0] = p.x; f[1] = p.y;
    p = __half22float2(*reinterpret_cast<__half2*>(&raw.y)); f[2] = p.x; f[3] = p.y;
    p = __half22float2(*reinterpret_cast<__half2*>(&raw.z)); f[4] = p.x; f[5] = p.y;
    p = __half22float2(*reinterpret_cast<__half2*>(&raw.w)); f[6] = p.x; f[7] = p.y;
}

// ---------------- preprocessing (R9-proven) ----------------
__global__ void k_convzero(const float* __restrict__ x) {
    int i = blockIdx.x * blockDim.x + threadIdx.x;   // [0, NN*8)
    if (i < NN * 8) {
        const float4* xp = reinterpret_cast<const float4*>(x) + (size_t)i * 2;
        float4 a = xp[0], b = xp[1];
        uint4 o;
        *reinterpret_cast<__half2*>(&o.x) = __floats2half2_rn(a.x, a.y);
        *reinterpret_cast<__half2*>(&o.y) = __floats2half2_rn(a.z, a.w);
        *reinterpret_cast<__half2*>(&o.z) = __floats2half2_rn(b.x, b.y);
        *reinterpret_cast<__half2*>(&o.w) = __floats2half2_rn(b.z, b.w);
        reinterpret_cast<uint4*>(g_x16)[i] = o;
    }
    if (i < NN) { g_outdeg[i] = 0; g_indeg[i] = 0; }
}

__global__ void k_degree(const int* __restrict__ src, const int* __restrict__ dst) {
    int e = blockIdx.x * blockDim.x + threadIdx.x;
    if (e < EE) {
        atomicAdd(&g_outdeg[src[e]], 1);
        atomicAdd(&g_indeg[dst[e]], 1);
    }
}

__global__ void k_scan_blk() {
    __shared__ int sh[1024];
    int t = threadIdx.x;
    int i = blockIdx.x * 1024 + t;
    int deg = (i < NN) ? g_indeg[i] : 0;
    if (i < NN) {
        g_norm_dst[i] = rsqrtf((float)max(deg, 1));
        g_norm_src[i] = rsqrtf((float)max(g_outdeg[i], 1));
    }
    sh[t] = deg;
    __syncthreads();
    #pragma unroll
    for (int off = 1; off < 1024; off <<= 1) {
        int x = (t >= off) ? sh[t - off] : 0;
        __syncthreads();
        sh[t] += x;
        __syncthreads();
    }
    if (i < NN) g_rowptr[i + 1] = sh[t];
    if (t == 1023) g_bsum[blockIdx.x] = sh[1023];
}

__global__ void k_scan_add() {
    __shared__ int off;
    int t = threadIdx.x;
    int i = blockIdx.x * 1024 + t;
    if (t < 32) {
        int s = 0;
        for (int b = t; b < blockIdx.x; b += 32) s += g_bsum[b];
        #pragma unroll
        for (int o = 16; o > 0; o >>= 1) s += __shfl_down_sync(0xFFFFFFFFu, s, o);
        if (t == 0) off = s;
    }
    __syncthreads();
    if (i < NN) {
        int v = g_rowptr[i + 1] + off;
        g_rowptr[i + 1] = v;
        if (i + 1 < NN) g_cursor[i + 1] = v;
        if (i == 0) { g_rowptr[0] = 0; g_cursor[0] = 0; }
    }
}

__global__ void k_scatter(const int* __restrict__ src, const int* __restrict__ dst) {
    int e = blockIdx.x * blockDim.x + threadIdx.x;
    if (e < EE) {
        int pos = atomicAdd(&g_cursor[dst[e]], 1);
        g_esrc[pos] = src[e];
    }
}

// ---------------- aggregation (exact R9: 4 slots x 8 lanes, unroll 2) ----------------
template <bool LAYER1>
__global__ void __launch_bounds__(256) k_agg(const float* __restrict__ bias,
                                             float* __restrict__ out_arg) {
    const uint4* __restrict__ feat = LAYER1
        ? reinterpret_cast<const uint4*>(g_x16)
        : reinterpret_cast<const uint4*>(g_h2);
    int n = blockIdx.x * 8 + (threadIdx.x >> 5);   // grid*8 == NN
    int lane = threadIdx.x & 31;
    int slot = lane >> 3;
    int fl   = lane & 7;

    int s = g_rowptr[n], e = g_rowptr[n + 1];
    float acc[8] = {0.f, 0.f, 0.f, 0.f, 0.f, 0.f, 0.f, 0.f};
    #pragma unroll 2
    for (int j = s + slot; j < e; j += 4) {
        int u = g_esrc[j];
        uint4 raw = feat[(size_t)u * 8 + fl];
        float f[8];
        h8_to_f8(raw, f);
        if (LAYER1) {
            float sc = g_norm_src[u];
            #pragma unroll
            for (int k = 0; k < 8; k++) acc[k] = fmaf(f[k], sc, acc[k]);
        } else {
            #pragma unroll
            for (int k = 0; k < 8; k++) acc[k] += f[k];
        }
    }
    #pragma unroll
    for (int o = 16; o >= 8; o >>= 1)
        #pragma unroll
        for (int k = 0; k < 8; k++)
            acc[k] += __shfl_down_sync(0xFFFFFFFFu, acc[k], o);

    if (slot == 0) {
        if (LAYER1) {
            uint4 o;
            *reinterpret_cast<__half2*>(&o.x) = __floats2half2_rn(acc[0], acc[1]);
            *reinterpret_cast<__half2*>(&o.y) = __floats2half2_rn(acc[2], acc[3]);
            *reinterpret_cast<__half2*>(&o.z) = __floats2half2_rn(acc[4], acc[5]);
            *reinterpret_cast<__half2*>(&o.w) = __floats2half2_rn(acc[6], acc[7]);
            reinterpret_cast<uint4*>(g_agg1)[(size_t)n * 8 + fl] = o;
        } else {
            float nd = g_norm_dst[n];
            float4 b0 = reinterpret_cast<const float4*>(bias)[fl * 2];
            float4 b1 = reinterpret_cast<const float4*>(bias)[fl * 2 + 1];
            float* op = out_arg + (size_t)n * 64 + fl * 8;
            *reinterpret_cast<float4*>(op) = make_float4(
                fmaf(acc[0], nd, b0.x), fmaf(acc[1], nd, b0.y),
                fmaf(acc[2], nd, b0.z), fmaf(acc[3], nd, b0.w));
            *reinterpret_cast<float4*>(op + 4) = make_float4(
                fmaf(acc[4], nd, b1.x), fmaf(acc[5], nd, b1.y),
                fmaf(acc[6], nd, b1.z), fmaf(acc[7], nd, b1.w));
        }
    }
}

// ---------------- FUSED GEMM: h2 = ((relu((agg1@W1)*nd + b1)) * ns) @ W2 ----------------
// Block tile: 128 rows. Phase A: 128x128 = agg1[128,64] @ W1[64,128].
// Phase B: h1 epilogue -> tf32 smem (overlays As/Ws1 region). Phase C: [128,128]@W2[128,64].
// smem (floats): region0 = max(As 128*76 + Ws1 64*132, H1s 128*132) = 18176
//                Ws2 128*68 = 8704 | sb1 128 | sns 128  -> total 27136 floats (106 KB)
#define F_AS_STRIDE  76
#define F_WS1_OFF    (128 * F_AS_STRIDE)       // 9728
#define F_WS1_STRIDE 132
#define F_H1_STRIDE  132
#define F_WS2_OFF    18176
#define F_WS2_STRIDE 68
#define F_SB1_OFF    (F_WS2_OFF + 128 * F_WS2_STRIDE)   // 26880
#define F_SNS_OFF    (F_SB1_OFF + 128)                  // 27008
#define F_SMEM       ((F_SNS_OFF + 128) * 4)            // 108544 B

__global__ void __launch_bounds__(256) k_gemm_fused(const float* __restrict__ W1,
                                                    const float* __restrict__ b1,
                                                    const float* __restrict__ W2) {
    extern __shared__ float sm[];
    float* As  = sm;                 // phase A
    float* Ws1 = sm + F_WS1_OFF;     // phase A
    float* H1s = sm;                 // phase B/C (overlays As+Ws1)
    float* Ws2 = sm + F_WS2_OFF;
    float* sb1 = sm + F_SB1_OFF;
    float* sns = sm + F_SNS_OFF;

    int tid = threadIdx.x;
    int row0 = blockIdx.x * 128;

    // ---- loads: As (agg1 fp16 -> tf32), Ws1, Ws2, sb1, sns ----
    #pragma unroll
    for (int it = 0; it < 4; it++) {
        int idx = tid + it * 256;            // [0,1024)
        int r = idx >> 3, c8 = idx & 7;
        int row = row0 + r;
        float f[8] = {0.f, 0.f, 0.f, 0.f, 0.f, 0.f, 0.f, 0.f};
        if (row < NN) {
            uint4 raw = reinterpret_cast<const uint4*>(g_agg1)[(size_t)row * 8 + c8];
            h8_to_f8(raw, f);
        }
        float* p = &As[r * F_AS_STRIDE + c8 * 8];
        #pragma unroll
        for (int k = 0; k < 8; k++) p[k] = __uint_as_float(f2tf32(f[k]));
    }
    #pragma unroll
    for (int it = 0; it < 8; it++) {
        int idx4 = tid + it * 256;           // [0,2048)
        int k = idx4 >> 5, c4 = idx4 & 31;
        float4 v = *reinterpret_cast<const float4*>(&W1[(size_t)k * 128 + c4 * 4]);
        float* p = &Ws1[k * F_WS1_STRIDE + c4 * 4];
        p[0] = __uint_as_float(f2tf32(v.x)); p[1] = __uint_as_float(f2tf32(v.y));
        p[2] = __uint_as_float(f2tf32(v.z)); p[3] = __uint_as_float(f2tf32(v.w));
    }
    #pragma unroll
    for (int it = 0; it < 8; it++) {
        int idx4 = tid + it * 256;           // [0,2048)
        int k = idx4 >> 4, c4 = idx4 & 15;
        float4 v = *reinterpret_cast<const float4*>(&W2[(size_t)k * 64 + c4 * 4]);
        float* p = &Ws2[k * F_WS2_STRIDE + c4 * 4];
        p[0] = __uint_as_float(f2tf32(v.x)); p[1] = __uint_as_float(f2tf32(v.y));
        p[2] = __uint_as_float(f2tf32(v.z)); p[3] = __uint_as_float(f2tf32(v.w));
    }
    if (tid < 128) {
        sb1[tid] = b1[tid];
        int row = row0 + tid;
        sns[tid] = (row < NN) ? g_norm_src[row] : 0.f;
    }
    __syncthreads();

    int w = tid >> 5, lane = tid & 31;
    int wr = w >> 1, wc = w & 1;             // 4x2 warp grid
    int g = lane >> 2, t4 = lane & 3;

    const uint32_t* Au = reinterpret_cast<const uint32_t*>(As);
    const uint32_t* W1u = reinterpret_cast<const uint32_t*>(Ws1);

    // ---- Phase A: MMA1 (K=64) -> c1[2][8][4] (warp: 32r x 64c of 128x128) ----
    float c1[2][8][4];
    #pragma unroll
    for (int i = 0; i < 2; i++)
        #pragma unroll
        for (int j = 0; j < 8; j++)
            #pragma unroll
            for (int q = 0; q < 4; q++) c1[i][j][q] = 0.f;

    #pragma unroll
    for (int ks = 0; ks < 8; ks++) {
        int kb = ks * 8;
        uint32_t a[2][4];
        #pragma unroll
        for (int rf = 0; rf < 2; rf++) {
            int R = wr * 32 + rf * 16;
            a[rf][0] = Au[(R + g) * F_AS_STRIDE + kb + t4];
            a[rf][1] = Au[(R + 8 + g) * F_AS_STRIDE + kb + t4];
            a[rf][2] = Au[(R + g) * F_AS_STRIDE + kb + 4 + t4];
            a[rf][3] = Au[(R + 8 + g) * F_AS_STRIDE + kb + 4 + t4];
        }
        #pragma unroll
        for (int cf = 0; cf < 8; cf++) {
            int C = wc * 64 + cf * 8 + g;
            uint32_t b0 = W1u[(kb + t4) * F_WS1_STRIDE + C];
            uint32_t b1r = W1u[(kb + 4 + t4) * F_WS1_STRIDE + C];
            #pragma unroll
            for (int rf = 0; rf < 2; rf++)
                MMA_TF32(c1[rf][cf][0], c1[rf][cf][1], c1[rf][cf][2], c1[rf][cf][3],
                         a[rf][0], a[rf][1], a[rf][2], a[rf][3], b0, b1r);
        }
    }
    __syncthreads();   // all As/Ws1 reads complete before overlay write

    // ---- Phase B: h1 = relu(c1*nd + b1); h1s = h1*ns -> tf32 smem ----
    #pragma unroll
    for (int rf = 0; rf < 2; rf++) {
        int lr1 = wr * 32 + rf * 16 + g;
        int lr2 = lr1 + 8;
        int r1 = row0 + lr1, r2 = row0 + lr2;
        float nd1 = (r1 < NN) ? g_norm_dst[r1] : 0.f;
        float nd2 = (r2 < NN) ? g_norm_dst[r2] : 0.f;
        float ns1 = sns[lr1], ns2 = sns[lr2];
        #pragma unroll
        for (int cf = 0; cf < 8; cf++) {
            int col = wc * 64 + cf * 8 + 2 * t4;
            float bx = sb1[col], by = sb1[col + 1];
            float v;
            v = fmaxf(fmaf(c1[rf][cf][0], nd1, bx), 0.f) * ns1;
            H1s[lr1 * F_H1_STRIDE + col]     = __uint_as_float(f2tf32(v));
            v = fmaxf(fmaf(c1[rf][cf][1], nd1, by), 0.f) * ns1;
            H1s[lr1 * F_H1_STRIDE + col + 1] = __uint_as_float(f2tf32(v));
            v = fmaxf(fmaf(c1[rf][cf][2], nd2, bx), 0.f) * ns2;
            H1s[lr2 * F_H1_STRIDE + col]     = __uint_as_float(f2tf32(v));
            v = fmaxf(fmaf(c1[rf][cf][3], nd2, by), 0.f) * ns2;
            H1s[lr2 * F_H1_STRIDE + col + 1] = __uint_as_float(f2tf32(v));
        }
    }
    __syncthreads();

    // ---- Phase C: MMA2 (K=128) over H1s, Ws2 -> c2[2][4][4] (warp: 32r x 32c of 128x64) ----
    const uint32_t* Hu = reinterpret_cast<const uint32_t*>(H1s);
    const uint32_t* W2u = reinterpret_cast<const uint32_t*>(Ws2);

    float c2[2][4][4];
    #pragma unroll
    for (int i = 0; i < 2; i++)
        #pragma unroll
        for (int j = 0; j < 4; j++)
            #pragma unroll
            for (int q = 0; q < 4; q++) c2[i][j][q] = 0.f;

    #pragma unroll
    for (int ks = 0; ks < 16; ks++) {
        int kb = ks * 8;
        uint32_t a[2][4];
        #pragma unroll
        for (int rf = 0; rf < 2; rf++) {
            int R = wr * 32 + rf * 16;
            a[rf][0] = Hu[(R + g) * F_H1_STRIDE + kb + t4];
            a[rf][1] = Hu[(R + 8 + g) * F_H1_STRIDE + kb + t4];
            a[rf][2] = Hu[(R + g) * F_H1_STRIDE + kb + 4 + t4];
            a[rf][3] = Hu[(R + 8 + g) * F_H1_STRIDE + kb + 4 + t4];
        }
        #pragma unroll
        for (int cf = 0; cf < 4; cf++) {
            int C = wc * 32 + cf * 8 + g;
            uint32_t b0 = W2u[(kb + t4) * F_WS2_STRIDE + C];
            uint32_t b1r = W2u[(kb + 4 + t4) * F_WS2_STRIDE + C];
            #pragma unroll
            for (int rf = 0; rf < 2; rf++)
                MMA_TF32(c2[rf][cf][0], c2[rf][cf][1], c2[rf][cf][2], c2[rf][cf][3],
                         a[rf][0], a[rf][1], a[rf][2], a[rf][3], b0, b1r);
        }
    }

    // ---- epilogue -> g_h2 (fp16) ----
    #pragma unroll
    for (int rf = 0; rf < 2; rf++) {
        int r1 = row0 + wr * 32 + rf * 16 + g;
        int r2 = r1 + 8;
        #pragma unroll
        for (int cf = 0; cf < 4; cf++) {
            int col = wc * 32 + cf * 8 + 2 * t4;
            if (r1 < NN)
                *reinterpret_cast<__half2*>(&g_h2[(size_t)r1 * 64 + col]) =
                    __floats2half2_rn(c2[rf][cf][0], c2[rf][cf][1]);
            if (r2 < NN)
                *reinterpret_cast<__half2*>(&g_h2[(size_t)r2 * 64 + col]) =
                    __floats2half2_rn(c2[rf][cf][2], c2[rf][cf][3]);
        }
    }
}

// ---------------- launch ----------------
extern "C" void kernel_launch(void* const* d_in, const int* in_sizes, int n_in,
                              void* d_out, int out_size) {
    const float* x   = (const float*)d_in[0];
    const float* W1  = (const float*)d_in[1];
    const float* b1  = (const float*)d_in[2];
    const float* W2  = (const float*)d_in[3];
    const float* b2  = (const float*)d_in[4];
    const int*   src = (const int*)d_in[5];
    const int*   dst = (const int*)d_in[6];
    float* out = (float*)d_out;

    cudaFuncSetAttribute(k_gemm_fused, cudaFuncAttributeMaxDynamicSharedMemorySize, F_SMEM);

    k_convzero<<<(NN * 8 + 255) / 256, 256>>>(x);
    k_degree<<<(EE + 255) / 256, 256>>>(src, dst);
    k_scan_blk<<<SCAN_BLK, 1024>>>();
    k_scan_add<<<SCAN_BLK, 1024>>>();
    k_scatter<<<(EE + 255) / 256, 256>>>(src, dst);

    int ntiles = (NN + 127) / 128;   // 391
    k_agg<true><<<NN / 8, 256>>>(nullptr, nullptr);
    k_gemm_fused<<<ntiles, 256, F_SMEM>>>(W1, b1, W2);
    k_agg<false><<<NN / 8, 256>>>(b2, out);
}